// round 6
// baseline (speedup 1.0000x reference)
#include <cuda_runtime.h>

// SSIM-style loss (sum over channels+window, /ws^2), single fused kernel.
// x, y: (32, 3, 512, 512) fp32. out: (32,) fp32.
//
// Grid 1024 = (batch, window-row), 128 threads (float4 column t), one wave
// at 7 CTA/SM. STREAM-SEPARATED loads: per (channel, row-half), each warp
// first sweeps 16KB of x linearly (8 rows held in registers), then sweeps
// the matching 16KB of y, computing sxy against the retained x. Longer
// per-stream DRAM bursts, half the concurrent streams.
// Per-batch ticket: last CTA of each batch folds 32 row-partials -> out[b].

#define IMG_H 512
#define IMG_W 512
#define NCH 3
#define WS 16
#define NWIN_X 32
#define NWIN_Y 32
#define NBATCH 32
#define W4 (IMG_W / 4)

static __device__ float        g_partial[NBATCH * NWIN_Y];
static __device__ unsigned int g_ticket[NBATCH];

__global__ __launch_bounds__(128, 7)
void ssim_fused_kernel(const float* __restrict__ x, const float* __restrict__ y,
                       float* __restrict__ out) {
    const int t  = threadIdx.x;            // float4 column 0..127
    const int br = blockIdx.x & 31;        // window row
    const int b  = blockIdx.x >> 5;        // batch

    const size_t img = (size_t)NCH * IMG_H * IMG_W;
    const float4* __restrict__ xp = (const float4*)(x + (size_t)b * img);
    const float4* __restrict__ yp = (const float4*)(y + (size_t)b * img);

    float sx = 0.f, sy = 0.f, sxx = 0.f, syy = 0.f, sxy = 0.f;

#pragma unroll
    for (int c = 0; c < NCH; ++c) {
#pragma unroll
        for (int half = 0; half < 2; ++half) {
            const size_t base = (size_t)c * (IMG_H * W4)
                              + (size_t)(br * WS + half * 8) * W4 + t;

            // ---- pure x sweep: 8 rows = 16KB linear per warp ----
            float4 X[8];
#pragma unroll
            for (int j = 0; j < 8; ++j)
                X[j] = __ldcs(xp + base + (size_t)j * W4);
#pragma unroll
            for (int j = 0; j < 8; ++j) {
                sx += (X[j].x + X[j].y) + (X[j].z + X[j].w);
                sxx = fmaf(X[j].x, X[j].x, sxx); sxx = fmaf(X[j].y, X[j].y, sxx);
                sxx = fmaf(X[j].z, X[j].z, sxx); sxx = fmaf(X[j].w, X[j].w, sxx);
            }

            // ---- pure y sweep: 8 rows = 16KB linear, in 4-row sub-batches ----
#pragma unroll
            for (int j0 = 0; j0 < 8; j0 += 4) {
                float4 Y[4];
#pragma unroll
                for (int j = 0; j < 4; ++j)
                    Y[j] = __ldcs(yp + base + (size_t)(j0 + j) * W4);
#pragma unroll
                for (int j = 0; j < 4; ++j) {
                    const float4 xv = X[j0 + j];
                    sy += (Y[j].x + Y[j].y) + (Y[j].z + Y[j].w);
                    syy = fmaf(Y[j].x, Y[j].x, syy); syy = fmaf(Y[j].y, Y[j].y, syy);
                    syy = fmaf(Y[j].z, Y[j].z, syy); syy = fmaf(Y[j].w, Y[j].w, syy);
                    sxy = fmaf(xv.x, Y[j].x, sxy);   sxy = fmaf(xv.y, Y[j].y, sxy);
                    sxy = fmaf(xv.z, Y[j].z, sxy);   sxy = fmaf(xv.w, Y[j].w, sxy);
                }
            }
        }
    }

    // fold 4 adjacent threads (one 16-col window)
#pragma unroll
    for (int off = 1; off < 4; off <<= 1) {
        sx  += __shfl_xor_sync(0xffffffffu, sx,  off);
        sy  += __shfl_xor_sync(0xffffffffu, sy,  off);
        sxx += __shfl_xor_sync(0xffffffffu, sxx, off);
        syy += __shfl_xor_sync(0xffffffffu, syy, off);
        sxy += __shfl_xor_sync(0xffffffffu, sxy, off);
    }

    __shared__ float s_ssim[NWIN_X];
    __shared__ unsigned int s_ticket;
    if ((t & 3) == 0) {
        const float inv = 1.0f / (WS * WS);
        const float C1 = 6.5025f;
        const float C2 = 58.5225f;
        float mx = sx * inv, my = sy * inv;
        float vx = sxx * inv - mx * mx;
        float vy = syy * inv - my * my;
        float cv = sxy * inv - mx * my;
        float num = (2.0f * mx * my + C1) * (2.0f * cv + C2);
        float den = (mx * mx + my * my + C1) * (vx + vy + C2);
        s_ssim[t >> 2] = num / den;
    }
    __syncthreads();

    if (t < 32) {
        float v = s_ssim[t];
#pragma unroll
        for (int off = 16; off; off >>= 1)
            v += __shfl_xor_sync(0xffffffffu, v, off);
        if (t == 0) {
            g_partial[blockIdx.x] = v;
            __threadfence();
            unsigned int tk = atomicAdd(&g_ticket[b], 1u);
            s_ticket = tk;
        }
    }
    __syncthreads();

    // Last CTA of this batch folds the 32 row-partials.
    if (s_ticket == NWIN_Y - 1) {
        if (t < 32) {
            volatile float* vp = (volatile float*)&g_partial[b * NWIN_Y];
            float v = vp[t];
#pragma unroll
            for (int off = 16; off; off >>= 1)
                v += __shfl_xor_sync(0xffffffffu, v, off);
            if (t == 0) {
                out[b] = (1.0f - v * (1.0f / (NWIN_X * NWIN_Y))) * 0.5f;
                g_ticket[b] = 0u;   // reset for next (graph-replayed) launch
            }
        }
    }
}

extern "C" void kernel_launch(void* const* d_in, const int* in_sizes, int n_in,
                              void* d_out, int out_size) {
    const float* x = (const float*)d_in[0];
    const float* y = (const float*)d_in[1];
    float* out = (float*)d_out;
    (void)in_sizes; (void)n_in; (void)out_size;

    ssim_fused_kernel<<<NBATCH * NWIN_Y, 128>>>(x, y, out);
}